// round 7
// baseline (speedup 1.0000x reference)
#include <cuda_runtime.h>
#include <cstdint>

// GRU: B=64, T=2048, I=256, H=256
// out = concat( out[B,T,H], hN[B,H] ) fp32
//
// 16 clusters x 8 CTAs (128 SMs). Cluster c owns batches [4c,4c+4).
// CTA rank r owns j in [32r,32r+32) => fused weight rows {j,256+j,512+j},
// 96 rows x 512 cols fp32 = 192KB in SMEM.
//
// Pipelined step (hides cluster barrier + half the GEMM off the h-critical path):
//   GEMM-H(t)  [h(t) . W_hh slice, K=256]
//   __syncthreads
//   elementwise GRU -> out, broadcast h(t+1) slice to all 8 CTAs (DSMEM)
//   barrier.cluster.arrive
//   cp.async.wait + __syncthreads          (x(t+1) ready)
//   GEMM-I(t+1) [x(t+1) . W_ih slice, K=256]  -- independent of peers
//   cp.async prefetch x(t+2)
//   barrier.cluster.wait

static constexpr int B_  = 64;
static constexpr int T_  = 2048;
static constexpr int I_  = 256;
static constexpr int H_  = 256;

static constexpr int CL      = 8;
static constexpr int NB      = 4;
static constexpr int NCL     = 16;
static constexpr int THREADS = 384;
static constexpr int APS     = 520;   // A-panel row stride (floats), bank-stagger
static constexpr int RPC     = 96;    // weight rows per CTA
static constexpr int NK4     = 128;   // float4 chunks along K=512

// SMEM layout (floats)
static constexpr int OFF_W    = 0;                        // 96*512 = 49152
static constexpr int OFF_AP   = 49152;                    // 2*4*520 = 4160
static constexpr int OFF_ACCH = OFF_AP + 2 * NB * APS;    // 384
static constexpr int OFF_ACCI = OFF_ACCH + RPC * NB;      // 2*384 (double buffered)
static constexpr int OFF_BH   = OFF_ACCI + 2 * RPC * NB;  // 96
static constexpr int OFF_BI   = OFF_BH + RPC;             // 96
static constexpr int SMEM_FLOATS = OFF_BI + RPC;          // 54656
static constexpr int SMEM_BYTES  = SMEM_FLOATS * 4;       // 218624

typedef unsigned long long u64;

__device__ __forceinline__ void fma2(u64 &acc, u64 a, u64 b) {
    asm("fma.rn.f32x2 %0, %1, %2, %0;" : "+l"(acc) : "l"(a), "l"(b));
}
__device__ __forceinline__ float sum2(u64 v) {
    float lo, hi;
    asm("mov.b64 {%0,%1}, %2;" : "=f"(lo), "=f"(hi) : "l"(v));
    return lo + hi;
}
__device__ __forceinline__ uint32_t smem_u32(const void* p) {
    return (uint32_t)__cvta_generic_to_shared(p);
}
__device__ __forceinline__ void st_remote_f32(uint32_t laddr, int rank, float v) {
    uint32_t raddr;
    asm("mapa.shared::cluster.u32 %0, %1, %2;" : "=r"(raddr) : "r"(laddr), "r"(rank));
    asm volatile("st.shared::cluster.f32 [%0], %1;" :: "r"(raddr), "f"(v));
}
__device__ __forceinline__ void cluster_arrive_() {
    asm volatile("barrier.cluster.arrive.aligned;" ::: "memory");
}
__device__ __forceinline__ void cluster_wait_() {
    asm volatile("barrier.cluster.wait.aligned;" ::: "memory");
}
__device__ __forceinline__ uint32_t ctarank_() {
    uint32_t r;
    asm("mov.u32 %0, %%cluster_ctarank;" : "=r"(r));
    return r;
}
__device__ __forceinline__ float sigmoidf_(float x) {
    return 1.0f / (1.0f + __expf(-x));
}
__device__ __forceinline__ float tanhf_fast_(float x) {
    // tanh(x) = 1 - 2/(1+exp(2x)); exact limits at +-inf, ~1e-6 rel err
    return 1.0f - 2.0f / (1.0f + __expf(2.0f * x));
}

__global__ void __launch_bounds__(THREADS, 1) __cluster_dims__(CL, 1, 1)
gru_persistent_kernel(const float* __restrict__ x,
                      const float* __restrict__ h0,
                      const float* __restrict__ Wih,
                      const float* __restrict__ bih,
                      const float* __restrict__ Whh,
                      const float* __restrict__ bhh,
                      float* __restrict__ out,
                      int out_size)
{
    extern __shared__ float smem[];
    float* Ws   = smem + OFF_W;     // [k4][96 rows][4 floats], k4<64: W_hh, k4>=64: W_ih
    float* Ap   = smem + OFF_AP;    // [2 parity][NB][APS]; [0:256)=h, [256:512)=x
    float* accH = smem + OFF_ACCH;  // [96][4]
    float* accI = smem + OFF_ACCI;  // [2 parity][96][4]
    float* bHs  = smem + OFF_BH;
    float* bIs  = smem + OFF_BI;

    const int tid  = threadIdx.x;
    const int rank = (int)ctarank_();
    const int b0   = (blockIdx.x >> 3) * NB;

    const uint32_t ap_u32 = smem_u32(Ap);

    // ---- init: weight slice [96 x 512] into SMEM, layout Ws[k4][lr][4]
    for (int idx = tid; idx < RPC * NK4; idx += THREADS) {
        int lr = idx >> 7;
        int k4 = idx & 127;
        int g  = ((lr >> 5) << 8) + (rank << 5) + (lr & 31);
        int k0 = k4 << 2;
        float4 v;
        if (k0 < 256) v = *(const float4*)(Whh + (size_t)g * H_ + k0);
        else          v = *(const float4*)(Wih + (size_t)g * I_ + (k0 - 256));
        *(float4*)(Ws + ((k4 * RPC + lr) << 2)) = v;
    }
    for (int lr = tid; lr < RPC; lr += THREADS) {
        int g = ((lr >> 5) << 8) + (rank << 5) + (lr & 31);
        bHs[lr] = bhh[g];
        bIs[lr] = bih[g];
    }
    // h0 and x(0) into parity-0 A-panel
    for (int i4 = tid; i4 < NB * 64; i4 += THREADS) {
        int b = i4 >> 6, kk = i4 & 63;
        *(float4*)(Ap + b * APS + (kk << 2)) =
            *(const float4*)(h0 + (size_t)(b0 + b) * H_ + (kk << 2));
        *(float4*)(Ap + b * APS + 256 + (kk << 2)) =
            *(const float4*)(x + ((size_t)(b0 + b) * T_ + 0) * I_ + (kk << 2));
    }
    cluster_arrive_();
    cluster_wait_();

    // GEMM mapping: gb = batch, r = local weight row (one per thread)
    const int gb = tid & 3;
    const int r  = tid >> 2;        // 0..95
    const ulonglong2* W2 = (const ulonglong2*)Ws;

    // elementwise mapping (tid < 128): coalesced out stores
    const int eb = tid >> 5;        // batch 0..3
    const int ej = tid & 31;        // j within slice

    // ---- prologue: accI for t=0 from x(0); prefetch x(1) -> Ap[1].x
    {
        const ulonglong2* A2 = (const ulonglong2*)(Ap + gb * APS + 256);
        u64 ia = 0, ib = 0;
        #pragma unroll 8
        for (int k4 = 0; k4 < 64; ++k4) {
            ulonglong2 a = A2[k4];
            ulonglong2 w = W2[(k4 + 64) * RPC + r];
            fma2(ia, a.x, w.x); fma2(ib, a.y, w.y);
        }
        accI[(r << 2) + gb] = sum2(ia) + sum2(ib);
    }
    for (int i4 = tid; i4 < NB * 64; i4 += THREADS) {
        int b = i4 >> 6, kk = i4 & 63;
        const float* g = x + ((size_t)(b0 + b) * T_ + 1) * I_ + (kk << 2);
        uint32_t s = ap_u32 + (uint32_t)(((NB * APS) + b * APS + 256 + (kk << 2)) * 4);
        asm volatile("cp.async.ca.shared.global [%0], [%1], 16;" :: "r"(s), "l"(g));
    }
    asm volatile("cp.async.commit_group;");

    const size_t BTH = (size_t)B_ * T_ * H_;

    for (int t = 0; t < T_; ++t) {
        const int p  = t & 1;
        const int pn = p ^ 1;

        // ---- 1. GEMM-H(t): gh = h(t) . W_hh-slice  (K=256)
        {
            const ulonglong2* A2 = (const ulonglong2*)(Ap + p * (NB * APS) + gb * APS);
            u64 ha = 0, hb = 0;
            #pragma unroll 8
            for (int k4 = 0; k4 < 64; ++k4) {
                ulonglong2 a = A2[k4];
                ulonglong2 w = W2[k4 * RPC + r];
                fma2(ha, a.x, w.x); fma2(hb, a.y, w.y);
            }
            accH[(r << 2) + gb] = sum2(ha) + sum2(hb);
        }
        __syncthreads();   // accH ready; also orders prev-iter accI / x-buffer reuse

        // ---- 2. elementwise GRU + h broadcast (128 threads)
        if (tid < 128) {
            const int b  = eb;
            const int jj = ej;
            const int jg = (rank << 5) + jj;
            const float* aI = accI + p * (RPC * NB);

            float gr = accH[(jj << 2) + b]        + bHs[jj];
            float ir = aI  [(jj << 2) + b]        + bIs[jj];
            float gc = accH[((32 + jj) << 2) + b] + bHs[32 + jj];
            float ic = aI  [((32 + jj) << 2) + b] + bIs[32 + jj];
            float gu = accH[((64 + jj) << 2) + b] + bHs[64 + jj];
            float iu = aI  [((64 + jj) << 2) + b] + bIs[64 + jj];

            float rg = sigmoidf_(ir + gr);
            float u  = sigmoidf_(iu + gu);
            float n  = tanhf_fast_(ic + rg * gc);

            float hold = Ap[p * (NB * APS) + b * APS + jg];
            float hy   = hold + u * (n - hold);

            out[((size_t)(b0 + b) * T_ + t) * H_ + jg] = hy;

            uint32_t laddr = ap_u32 + (uint32_t)((pn * (NB * APS) + b * APS + jg) * 4);
            #pragma unroll
            for (int pr = 0; pr < CL; ++pr)
                st_remote_f32(laddr, pr, hy);
        }

        // ---- 3. arrive (releases the DSMEM broadcasts cluster-wide)
        cluster_arrive_();

        // ---- 4. x(t+1) landed last iter; make it CTA-visible
        asm volatile("cp.async.wait_group 0;" ::: "memory");
        __syncthreads();

        // ---- 5. GEMM-I(t+1): gi = x(t+1) . W_ih-slice  (peer-independent,
        //         hides barrier latency + cross-CTA skew)
        if (t + 1 < T_) {
            const ulonglong2* A2 = (const ulonglong2*)(Ap + pn * (NB * APS) + gb * APS + 256);
            u64 ia = 0, ib = 0;
            #pragma unroll 8
            for (int k4 = 0; k4 < 64; ++k4) {
                ulonglong2 a = A2[k4];
                ulonglong2 w = W2[(k4 + 64) * RPC + r];
                fma2(ia, a.x, w.x); fma2(ib, a.y, w.y);
            }
            accI[pn * (RPC * NB) + (r << 2) + gb] = sum2(ia) + sum2(ib);
        }

        // ---- 6. prefetch x(t+2) into Ap[p].x
        if (t + 2 < T_) {
            for (int i4 = tid; i4 < NB * 64; i4 += THREADS) {
                int b = i4 >> 6, kk = i4 & 63;
                const float* g = x + ((size_t)(b0 + b) * T_ + (t + 2)) * I_ + (kk << 2);
                uint32_t s = ap_u32 + (uint32_t)((p * (NB * APS) + b * APS + 256 + (kk << 2)) * 4);
                asm volatile("cp.async.ca.shared.global [%0], [%1], 16;" :: "r"(s), "l"(g));
            }
        }
        asm volatile("cp.async.commit_group;");

        // ---- 7. wait: all peers' h(t+1) slices visible in Ap[pn].h
        cluster_wait_();
    }

    // ---- final hidden state: h(T) lives in parity 0 (T even)
    if (out_size >= (int)(BTH + (size_t)B_ * H_)) {
        for (int i = tid; i < NB * H_; i += THREADS) {
            int b = i >> 8, j = i & 255;
            out[BTH + (size_t)(b0 + b) * H_ + j] = Ap[b * APS + j];
        }
    }
}

extern "C" void kernel_launch(void* const* d_in, const int* in_sizes, int n_in,
                              void* d_out, int out_size) {
    const float* x    = (const float*)d_in[0];
    const float* h0   = (const float*)d_in[1];
    const float* Wih  = (const float*)d_in[2];
    const float* bih  = (const float*)d_in[3];
    const float* Whh  = (const float*)d_in[4];
    const float* bhh  = (const float*)d_in[5];
    float* out = (float*)d_out;

    cudaFuncSetAttribute(gru_persistent_kernel,
                         cudaFuncAttributeMaxDynamicSharedMemorySize, SMEM_BYTES);

    gru_persistent_kernel<<<NCL * CL, THREADS, SMEM_BYTES>>>(
        x, h0, Wih, bih, Whh, bhh, out, out_size);
}

// round 8
// speedup vs baseline: 2.2530x; 2.2530x over previous
#include <cuda_runtime.h>
#include <cstdint>

// GRU: B=64, T=2048, I=256, H=256.  out = concat(out[B,T,H], hN[B,H]) fp32.
//
// 16 clusters x 8 CTAs (128 SMs). Cluster c owns batches [4c,4c+4).
// CTA rank owns j in [32r,32r+32) => fused rows {j, 256+j, 512+j} of
// [W_hh | W_ih] (96 rows x 512 cols). Thread (r,kc) keeps a 128-float chunk
// of its row IN REGISTERS (zero weight SMEM traffic per step).
// Per step: 1 register-GEMM pass (A broadcast from SMEM) -> syncthreads ->
// elementwise GRU (128 thr) + x-prefetch cp.async (256 thr) -> DSMEM h
// broadcast -> cluster barrier.

static constexpr int B_  = 64;
static constexpr int T_  = 2048;
static constexpr int I_  = 256;
static constexpr int H_  = 256;

static constexpr int CL      = 8;
static constexpr int NB      = 4;
static constexpr int NCL     = 16;
static constexpr int THREADS = 384;   // 96 rows x 4 k-chunks
static constexpr int APS     = 520;   // A-panel row stride (floats)
static constexpr int ACS     = 5;     // acc row stride (floats) -> conflict-free

typedef unsigned long long u64;

__device__ __forceinline__ void fma2(u64 &acc, u64 a, u64 b) {
    asm("fma.rn.f32x2 %0, %1, %2, %0;" : "+l"(acc) : "l"(a), "l"(b));
}
__device__ __forceinline__ float sum2(u64 v) {
    float lo, hi;
    asm("mov.b64 {%0,%1}, %2;" : "=f"(lo), "=f"(hi) : "l"(v));
    return lo + hi;
}
__device__ __forceinline__ uint32_t smem_u32(const void* p) {
    return (uint32_t)__cvta_generic_to_shared(p);
}
__device__ __forceinline__ void st_remote_f32(uint32_t laddr, int rank, float v) {
    uint32_t raddr;
    asm("mapa.shared::cluster.u32 %0, %1, %2;" : "=r"(raddr) : "r"(laddr), "r"(rank));
    asm volatile("st.shared::cluster.f32 [%0], %1;" :: "r"(raddr), "f"(v));
}
__device__ __forceinline__ void cluster_arrive_() {
    asm volatile("barrier.cluster.arrive.aligned;" ::: "memory");
}
__device__ __forceinline__ void cluster_wait_() {
    asm volatile("barrier.cluster.wait.aligned;" ::: "memory");
}
__device__ __forceinline__ uint32_t ctarank_() {
    uint32_t r;
    asm("mov.u32 %0, %%cluster_ctarank;" : "=r"(r));
    return r;
}
__device__ __forceinline__ float sigmoidf_(float x) {
    return 1.0f / (1.0f + __expf(-x));
}
__device__ __forceinline__ float tanhf_fast_(float x) {
    return 1.0f - 2.0f / (1.0f + __expf(2.0f * x));
}

__global__ void __launch_bounds__(THREADS, 1) __cluster_dims__(CL, 1, 1)
gru_persistent_kernel(const float* __restrict__ x,
                      const float* __restrict__ h0,
                      const float* __restrict__ Wih,
                      const float* __restrict__ bih,
                      const float* __restrict__ Whh,
                      const float* __restrict__ bhh,
                      float* __restrict__ out,
                      int out_size)
{
    __shared__ float Ap[2 * NB * APS];     // [parity][b][520]: h in [0,256), x in [256,512)
    __shared__ float accS[4 * 96 * ACS];   // [kc][row][b] partials, stride-5 rows
    __shared__ float bHs[96];
    __shared__ float bIs[96];

    const int tid  = threadIdx.x;
    const int rank = (int)ctarank_();
    const int b0   = (blockIdx.x >> 3) * NB;

    const int kc   = tid / 96;             // k-chunk 0..3 (uniform per warp: 96 = 3 warps)
    const int r    = tid - kc * 96;        // local row 0..95
    const int gate = r >> 5;
    const int g    = (gate << 8) + (rank << 5) + (r & 31);   // global fused row

    // ---- weights into registers: 32 x float4 = 128 floats (fused k in [128kc, 128kc+128))
    ulonglong2 w[32];
    {
        const float* Wsrc = ((kc < 2) ? Whh : Wih) + (size_t)g * 256 + (size_t)(kc & 1) * 128;
        #pragma unroll
        for (int k4 = 0; k4 < 32; ++k4)
            w[k4] = *(const ulonglong2*)(Wsrc + (k4 << 2));
    }

    // ---- biases to SMEM
    for (int i = tid; i < 96; i += THREADS) {
        int gg = ((i >> 5) << 8) + (rank << 5) + (i & 31);
        bHs[i] = bhh[gg];
        bIs[i] = bih[gg];
    }

    // ---- h0 + x(0) into Ap[0]
    for (int i4 = tid; i4 < NB * 64; i4 += THREADS) {
        int b = i4 >> 6, kk = i4 & 63;
        *(float4*)(Ap + b * APS + (kk << 2)) =
            *(const float4*)(h0 + (size_t)(b0 + b) * H_ + (kk << 2));
        *(float4*)(Ap + b * APS + 256 + (kk << 2)) =
            *(const float4*)(x + ((size_t)(b0 + b) * T_) * I_ + (kk << 2));
    }

    // ---- cp.async x(1) -> Ap[1].x
    const uint32_t ap_u32 = smem_u32(Ap);
    for (int i4 = tid; i4 < NB * 64; i4 += THREADS) {
        int b = i4 >> 6, kk = i4 & 63;
        const float* gsrc = x + ((size_t)(b0 + b) * T_ + 1) * I_ + (kk << 2);
        uint32_t s = ap_u32 + (uint32_t)(((NB * APS) + b * APS + 256 + (kk << 2)) * 4);
        asm volatile("cp.async.ca.shared.global [%0], [%1], 16;" :: "r"(s), "l"(gsrc));
    }
    asm volatile("cp.async.commit_group;");

    cluster_arrive_();
    cluster_wait_();

    const int koff = kc << 7;           // A-panel column base for this k-chunk
    const int eb   = tid >> 5;          // elementwise batch (tid<128)
    const int ej   = tid & 31;
    const int ejg  = (rank << 5) + ej;
    const size_t BTH = (size_t)B_ * T_ * H_;

    for (int t = 0; t < T_; ++t) {
        const int p  = t & 1;
        const int pn = p ^ 1;

        // ---- 1. register-GEMM pass: partial dot over this thread's 128-K chunk, 4 batches
        {
            const float* A = Ap + p * (NB * APS) + koff;
            u64 a0 = 0, a1 = 0, a2 = 0, a3 = 0;
            #pragma unroll
            for (int k4 = 0; k4 < 32; ++k4) {
                ulonglong2 wv = w[k4];
                ulonglong2 v0 = *(const ulonglong2*)(A + 0 * APS + (k4 << 2));
                ulonglong2 v1 = *(const ulonglong2*)(A + 1 * APS + (k4 << 2));
                fma2(a0, v0.x, wv.x); fma2(a0, v0.y, wv.y);
                fma2(a1, v1.x, wv.x); fma2(a1, v1.y, wv.y);
                ulonglong2 v2 = *(const ulonglong2*)(A + 2 * APS + (k4 << 2));
                ulonglong2 v3 = *(const ulonglong2*)(A + 3 * APS + (k4 << 2));
                fma2(a2, v2.x, wv.x); fma2(a2, v2.y, wv.y);
                fma2(a3, v3.x, wv.x); fma2(a3, v3.y, wv.y);
            }
            float* dst = accS + (kc * 96 + r) * ACS;
            dst[0] = sum2(a0); dst[1] = sum2(a1);
            dst[2] = sum2(a2); dst[3] = sum2(a3);
        }
        __syncthreads();

        // ---- 2a. elementwise GRU + DSMEM h-broadcast (threads 0..127)
        if (tid < 128) {
            const int b = eb, j = ej;
            #define AT(kci, row) accS[((kci) * 96 + (row)) * ACS + b]
            float rsum = AT(0, j)      + AT(1, j)      + AT(2, j)      + AT(3, j)
                       + bHs[j] + bIs[j];
            float hc   = AT(0, 32 + j) + AT(1, 32 + j) + bHs[32 + j];
            float ic   = AT(2, 32 + j) + AT(3, 32 + j) + bIs[32 + j];
            float usum = AT(0, 64 + j) + AT(1, 64 + j) + AT(2, 64 + j) + AT(3, 64 + j)
                       + bHs[64 + j] + bIs[64 + j];
            #undef AT

            float rg = sigmoidf_(rsum);
            float u  = sigmoidf_(usum);
            float n  = tanhf_fast_(ic + rg * hc);

            float hold = Ap[p * (NB * APS) + b * APS + ejg];
            float hy   = hold + u * (n - hold);

            out[((size_t)(b0 + b) * T_ + t) * H_ + ejg] = hy;

            uint32_t laddr = ap_u32 + (uint32_t)((pn * (NB * APS) + b * APS + ejg) * 4);
            #pragma unroll
            for (int pr = 0; pr < CL; ++pr)
                st_remote_f32(laddr, pr, hy);
        }
        // ---- 2b. x(t+2) prefetch into Ap[p].x (threads 128..383, one float4 each)
        else if (t + 2 < T_) {
            int i4 = tid - 128;                  // 0..255 = NB*64
            int b = i4 >> 6, kk = i4 & 63;
            const float* gsrc = x + ((size_t)(b0 + b) * T_ + (t + 2)) * I_ + (kk << 2);
            uint32_t s = ap_u32 + (uint32_t)((p * (NB * APS) + b * APS + 256 + (kk << 2)) * 4);
            asm volatile("cp.async.ca.shared.global [%0], [%1], 16;" :: "r"(s), "l"(gsrc));
        }
        asm volatile("cp.async.commit_group;");
        asm volatile("cp.async.wait_group 1;" ::: "memory");   // x(t+1) landed

        // ---- 3. cluster barrier: releases h-broadcasts + x visibility for t+1
        cluster_arrive_();
        cluster_wait_();
    }

    // ---- final hidden state: h(T) in parity 0 (T even)
    if (out_size >= (int)(BTH + (size_t)B_ * H_)) {
        for (int i = tid; i < NB * H_; i += THREADS) {
            int b = i >> 8, j = i & 255;
            out[BTH + (size_t)(b0 + b) * H_ + j] = Ap[b * APS + j];
        }
    }
}

extern "C" void kernel_launch(void* const* d_in, const int* in_sizes, int n_in,
                              void* d_out, int out_size) {
    const float* x    = (const float*)d_in[0];
    const float* h0   = (const float*)d_in[1];
    const float* Wih  = (const float*)d_in[2];
    const float* bih  = (const float*)d_in[3];
    const float* Whh  = (const float*)d_in[4];
    const float* bhh  = (const float*)d_in[5];
    float* out = (float*)d_out;

    gru_persistent_kernel<<<NCL * CL, THREADS>>>(
        x, h0, Wih, bih, Whh, bhh, out, out_size);
}